// round 14
// baseline (speedup 1.0000x reference)
#include <cuda_runtime.h>
#include <math.h>

#define Bmax 1024
#define Nn   100
#define Hh   128
#define NHEADS 8
#define HD   16
#define KTS  104        // KT stride (floats) = 26 f4
#define VTS  108        // VT stride = 27 f4
#define NP4  26
#define NPF  104
#define NEGV -1000000000.0f

// ---- device scratch ----
__device__ float g_Wcat[Hh * 512];
__device__ float g_Wqf [Hh * (Hh + 1)];
__device__ float g_Wq1 [Hh * Hh];
__device__ float g_qpool[Bmax * Hh];
__device__ float g_EncProj[(size_t)Bmax * 256 * Nn];   // [b][j][n]: K | V
__device__ float g_K2Wt[(size_t)Bmax * Nn * Hh];       // [b][n][h]
__device__ float g_QP  [(size_t)Bmax * Nn * Hh];       // [b][n][h]

// =====================================================================
__global__ void weights_kernel(const float* __restrict__ fc_w,
                               const float* __restrict__ fc1_w,
                               const float* __restrict__ Wq,
                               const float* __restrict__ Wk,
                               const float* __restrict__ Wv,
                               const float* __restrict__ Wo,
                               const float* __restrict__ Wk2)
{
    int bid = blockIdx.x, t = threadIdx.x;
    if (bid < 512) {
        int j = bid;
        float v;
        if (j < 128) {
            v = Wk[j * 128 + t];
        } else if (j < 256) {
            v = Wv[(j - 128) * 128 + t];
        } else if (j < 384) {
            int jp = j - 256;
            float s = 0.f;
            for (int h = 0; h < 128; h++) s += Wk2[h * 128 + t] * Wo[h * 128 + jp];
            v = s;
        } else {
            int hq = j - 384;
            float s = 0.f;
            for (int jj = 0; jj < 128; jj++) s += Wq[hq * 128 + jj] * fc_w[jj * 129 + t];
            v = s;
        }
        g_Wcat[t * 512 + j] = v;
    } else if (bid < 640) {
        int i = bid - 512;
        for (int k = t; k < 129; k += 128) {
            float s = 0.f;
            for (int j = 0; j < 128; j++) s += Wq[i * 128 + j] * fc_w[j * 129 + k];
            g_Wqf[i * 129 + k] = s;
        }
    } else {
        int i = bid - 640;
        float s = 0.f;
        for (int j = 0; j < 128; j++) s += Wq[i * 128 + j] * fc1_w[j * 128 + t];
        g_Wq1[i * 128 + t] = s;
    }
}

// =====================================================================
__global__ void qpool_kernel(const float* __restrict__ pool)
{
    int b = blockIdx.x, h = threadIdx.x;
    float s = 0.f;
    for (int k = 0; k < 128; k++) s += g_Wq1[h * 128 + k] * pool[b * 128 + k];
    g_qpool[b * 128 + h] = s;
}

// =====================================================================
__global__ __launch_bounds__(512, 1)
void encproj_kernel(const float* __restrict__ enc)
{
    extern __shared__ float As[];
    int b = blockIdx.x, t = threadIdx.x;
    for (int i = t; i < Nn * Hh; i += 512) As[i] = enc[(size_t)b * Nn * Hh + i];
    float w[128];
#pragma unroll
    for (int k = 0; k < 128; k++) w[k] = g_Wcat[k * 512 + t];
    __syncthreads();

    float* rowp = (t < 256) ? (g_EncProj + (size_t)b * 256 * Nn + (size_t)t * Nn) : 0;
    float* colp = (t < 384) ? (g_K2Wt + (size_t)b * Nn * Hh + (t - 256))
                            : (g_QP   + (size_t)b * Nn * Hh + (t - 384));

    for (int n0 = 0; n0 < Nn; n0 += 4) {
        float a0 = 0.f, a1 = 0.f, a2 = 0.f, a3 = 0.f;
        const float4* r0 = reinterpret_cast<const float4*>(&As[(n0 + 0) * Hh]);
        const float4* r1 = reinterpret_cast<const float4*>(&As[(n0 + 1) * Hh]);
        const float4* r2 = reinterpret_cast<const float4*>(&As[(n0 + 2) * Hh]);
        const float4* r3 = reinterpret_cast<const float4*>(&As[(n0 + 3) * Hh]);
#pragma unroll
        for (int kk = 0; kk < 32; kk++) {
            float4 x0 = r0[kk];
            a0 += x0.x * w[4*kk] + x0.y * w[4*kk+1] + x0.z * w[4*kk+2] + x0.w * w[4*kk+3];
            float4 x1 = r1[kk];
            a1 += x1.x * w[4*kk] + x1.y * w[4*kk+1] + x1.z * w[4*kk+2] + x1.w * w[4*kk+3];
            float4 x2 = r2[kk];
            a2 += x2.x * w[4*kk] + x2.y * w[4*kk+1] + x2.z * w[4*kk+2] + x2.w * w[4*kk+3];
            float4 x3 = r3[kk];
            a3 += x3.x * w[4*kk] + x3.y * w[4*kk+1] + x3.z * w[4*kk+2] + x3.w * w[4*kk+3];
        }
        if (t < 256) {
            reinterpret_cast<float4*>(rowp + n0)[0] = make_float4(a0, a1, a2, a3);
        } else {
            colp[(size_t)(n0 + 0) * Hh] = a0;
            colp[(size_t)(n0 + 1) * Hh] = a1;
            colp[(size_t)(n0 + 2) * Hh] = a2;
            colp[(size_t)(n0 + 3) * Hh] = a3;
        }
    }
}

// =====================================================================
// Kernel 4: dense decoder, 2 blocks/SM. K2 + QP from L2 (prefetched).
// =====================================================================
#define DEC_SMEM_FLOATS (Hh*KTS + Hh*VTS + NHEADS*NPF + 128 + 128 + 128 + NPF + NPF + NPF + 96 + 16)
#define DEC_SMEM_BYTES  (DEC_SMEM_FLOATS * 4)

__global__ __launch_bounds__(512, 2)
void decode_kernel(const float* __restrict__ capacity,
                   const float* __restrict__ demand,
                   const int*   __restrict__ Tptr,
                   float* __restrict__ out, int ns, int B)
{
    extern __shared__ float sm[];
    float* KT    = sm;                    // [128][104]
    float* VT    = KT   + Hh * KTS;       // [128][108]
    float* att   = VT   + Hh * VTS;       // [8][104]
    float* qp    = att  + NHEADS * NPF;   // 128
    float* wcap  = qp   + 128;            // 128
    float* g     = wcap + 128;            // 128
    float* dem   = g    + 128;            // 104
    float* mask1 = dem  + NPF;            // 104
    float* MSK   = mask1+ NPF;            // 104
    float* wred  = MSK  + NPF;            // 16 warps * stride 5 = 80 (+pad)
    float* misc  = wred + 96;             // [0]=cap [1]=base [2]=logp [3]=invT
    int*   imisc = (int*)(misc + 8);      // [0]=idx [1]=visited

    const int b = blockIdx.x, t = threadIdx.x;
    const int w = t >> 5, lane = t & 31;
    const int n3 = t >> 2, p43 = t & 3;   // R3 row / quarter
    const bool vrow = (n3 < Nn);

    // ---- load operands ----
    const float* ep = g_EncProj + (size_t)b * 256 * Nn;
    for (int i = t; i < 128 * KTS; i += 512) {
        int j = i / KTS, n = i - j * KTS;
        KT[i] = (n < Nn) ? ep[j * Nn + n] : 0.f;
    }
    for (int i = t; i < 128 * VTS; i += 512) {
        int j = i / VTS, n = i - j * VTS;
        VT[i] = (n < Nn) ? ep[(128 + j) * Nn + n] : 0.f;
    }
    if (t < 128) {
        qp[t]   = g_qpool[b * 128 + t];
        wcap[t] = g_Wqf[t * 129 + 128];
    }
    if (t < NPF) {
        dem[t]   = (t < Nn) ? demand[b * Nn + t] : 3.0e38f;
        mask1[t] = (t < Nn) ? 0.f : 1.f;
    }
    if (t == 0) {
        float c = capacity[b];
        misc[0] = c; misc[1] = capacity[0]; misc[2] = 0.f;
        misc[3] = 1.0f / (float)(*Tptr);
        imisc[0] = 0; imisc[1] = 0;
    }
    __syncthreads();

    // ---- initial mask (idx=0, mask1=0) : warp 0 ----
    if (w == 0) {
        float capc = misc[0];
        const int li = (lane < NP4) ? lane : 0;
        float4 dm = reinterpret_cast<const float4*>(dem)[li];
        float4 m1 = reinterpret_cast<const float4*>(mask1)[li];
        float4 mk;
        mk.x = (m1.x > 0.f || dm.x > capc) ? 1.f : 0.f;
        mk.y = (m1.y > 0.f || dm.y > capc) ? 1.f : 0.f;
        mk.z = (m1.z > 0.f || dm.z > capc) ? 1.f : 0.f;
        mk.w = (m1.w > 0.f || dm.w > capc) ? 1.f : 0.f;
        bool mine = true;
        if (lane < NP4) {
            if (lane > 0) mine = (mk.x > 0.f) && (mk.y > 0.f) && (mk.z > 0.f) && (mk.w > 0.f);
            else          mine = (mk.y > 0.f) && (mk.z > 0.f) && (mk.w > 0.f);
        }
        bool allc = __all_sync(0xffffffffu, mine);
        if (lane == 0) mk.x = allc ? 0.f : 1.f;
        if (lane < NP4) reinterpret_cast<float4*>(MSK)[lane] = mk;
    }
    __syncthreads();

    const float4* KT4  = reinterpret_cast<const float4*>(KT);
    const float4* VT4  = reinterpret_cast<const float4*>(VT);
    const float4* MSK4 = reinterpret_cast<const float4*>(MSK);
    const float4* g4   = reinterpret_cast<const float4*>(g);
    float4* att4 = reinterpret_cast<float4*>(att);

    const float* QPb = g_QP   + (size_t)b * Nn * Hh;
    const float4* K2p = reinterpret_cast<const float4*>(g_K2Wt + (size_t)b * Nn * Hh
                                                        + (size_t)(vrow ? n3 : 0) * Hh) + p43 * 8;

    for (int step = 0; step < ns; step++) {
        // ==== R1: q chunk (QP row from L2) + dense scores + softmax ====
        if (w < NHEADS) {
            int sidx = imisc[0];
            float capc = misc[0];
            float qd = 0.f;
            if (lane < HD) {
                int hh = w * HD + lane;
                qd = qp[hh] + QPb[(size_t)sidx * Hh + hh] + capc * wcap[hh];
            }
            float4 acc = make_float4(0.f, 0.f, 0.f, 0.f);
            const int li = (lane < NP4) ? lane : 0;
            const float4* kb = KT4 + (w * HD) * NP4;
#pragma unroll
            for (int d = 0; d < HD; d++) {
                float qv = __shfl_sync(0xffffffffu, qd, d);
                float4 kv = kb[d * NP4 + li];
                acc.x += qv * kv.x; acc.y += qv * kv.y;
                acc.z += qv * kv.z; acc.w += qv * kv.w;
            }
            float4 mv = MSK4[li];
            float4 v;
            v.x = (lane < NP4 && mv.x == 0.f) ? acc.x * 0.25f : NEGV;
            v.y = (lane < NP4 && mv.y == 0.f) ? acc.y * 0.25f : NEGV;
            v.z = (lane < NP4 && mv.z == 0.f) ? acc.z * 0.25f : NEGV;
            v.w = (lane < NP4 && mv.w == 0.f) ? acc.w * 0.25f : NEGV;
            float m = fmaxf(fmaxf(v.x, v.y), fmaxf(v.z, v.w));
#pragma unroll
            for (int off = 16; off; off >>= 1) m = fmaxf(m, __shfl_xor_sync(0xffffffffu, m, off));
            float4 e;
            e.x = expf(v.x - m); e.y = expf(v.y - m);
            e.z = expf(v.z - m); e.w = expf(v.w - m);
            float ss = e.x + e.y + e.z + e.w;
#pragma unroll
            for (int off = 16; off; off >>= 1) ss += __shfl_xor_sync(0xffffffffu, ss, off);
            float inv = 1.f / ss;
            if (lane < NP4)
                att4[w * NP4 + lane] = make_float4(e.x*inv, e.y*inv, e.z*inv, e.w*inv);
        }
        __syncthreads();

        // ==== prefetch first 4 K2 chunks (L2) — hidden under R2 ====
        float4 kvA0, kvA1, kvA2, kvA3;
        {
            kvA0 = vrow ? K2p[(0 + 2*p43) & 7] : make_float4(0,0,0,0);
            kvA1 = vrow ? K2p[(1 + 2*p43) & 7] : make_float4(0,0,0,0);
            kvA2 = vrow ? K2p[(2 + 2*p43) & 7] : make_float4(0,0,0,0);
            kvA3 = vrow ? K2p[(3 + 2*p43) & 7] : make_float4(0,0,0,0);
        }

        // ==== R2: g[h] = attn_head(h) · V[h] — one thread per h ====
        if (t < 128) {
            const float4* ap = att4 + (t >> 4) * NP4;
            const float4* vp = VT4 + t * 27;
            float sg = 0.f;
#pragma unroll
            for (int k = 0; k < NP4; k++) {
                float4 a = ap[k], vv = vp[k];
                sg += a.x*vv.x + a.y*vv.y + a.z*vv.z + a.w*vv.w;
            }
            g[t] = sg;
        }
        __syncthreads();

        // ==== R3: u row dot (K2 from L2) + per-warp argmax/logsumexp ====
        {
            float4 kvB0 = vrow ? K2p[(4 + 2*p43) & 7] : make_float4(0,0,0,0);
            float4 kvB1 = vrow ? K2p[(5 + 2*p43) & 7] : make_float4(0,0,0,0);
            float4 kvB2 = vrow ? K2p[(6 + 2*p43) & 7] : make_float4(0,0,0,0);
            float4 kvB3 = vrow ? K2p[(7 + 2*p43) & 7] : make_float4(0,0,0,0);
            float su = 0.f;
            {
                float4 gv;
                gv = g4[p43*8 + ((0 + 2*p43) & 7)];
                su += kvA0.x*gv.x + kvA0.y*gv.y + kvA0.z*gv.z + kvA0.w*gv.w;
                gv = g4[p43*8 + ((1 + 2*p43) & 7)];
                su += kvA1.x*gv.x + kvA1.y*gv.y + kvA1.z*gv.z + kvA1.w*gv.w;
                gv = g4[p43*8 + ((2 + 2*p43) & 7)];
                su += kvA2.x*gv.x + kvA2.y*gv.y + kvA2.z*gv.z + kvA2.w*gv.w;
                gv = g4[p43*8 + ((3 + 2*p43) & 7)];
                su += kvA3.x*gv.x + kvA3.y*gv.y + kvA3.z*gv.z + kvA3.w*gv.w;
                gv = g4[p43*8 + ((4 + 2*p43) & 7)];
                su += kvB0.x*gv.x + kvB0.y*gv.y + kvB0.z*gv.z + kvB0.w*gv.w;
                gv = g4[p43*8 + ((5 + 2*p43) & 7)];
                su += kvB1.x*gv.x + kvB1.y*gv.y + kvB1.z*gv.z + kvB1.w*gv.w;
                gv = g4[p43*8 + ((6 + 2*p43) & 7)];
                su += kvB2.x*gv.x + kvB2.y*gv.y + kvB2.z*gv.z + kvB2.w*gv.w;
                gv = g4[p43*8 + ((7 + 2*p43) & 7)];
                su += kvB3.x*gv.x + kvB3.y*gv.y + kvB3.z*gv.z + kvB3.w*gv.w;
            }
            su += __shfl_xor_sync(0xffffffffu, su, 1);
            su += __shfl_xor_sync(0xffffffffu, su, 2);

            // owner lanes (p43==0, valid row) hold u value
            float invT = misc[3];
            bool own = (p43 == 0) && vrow;
            float uval = NEGV;
            if (own) uval = (MSK[n3] == 0.f) ? 10.f * tanhf(su * 0.08838834764831845f) : NEGV;
            float vv = uval * invT;
            int   vi = own ? n3 : 0x7fffffff;
            // warp argmax over 8 owner lanes (xor 4,8,16)
            float bw = vv; int bi = vi;
#pragma unroll
            for (int off = 4; off <= 16; off <<= 1) {
                float ov = __shfl_xor_sync(0xffffffffu, bw, off);
                int   oi = __shfl_xor_sync(0xffffffffu, bi, off);
                if (ov > bw || (ov == bw && oi < bi)) { bw = ov; bi = oi; }
            }
            // warp expsum relative to warp max
            float ee = own ? expf(vv - bw) : 0.f;
#pragma unroll
            for (int off = 4; off <= 16; off <<= 1) ee += __shfl_xor_sync(0xffffffffu, ee, off);
            if (lane == 0) {
                wred[w * 5 + 0] = bw;
                wred[w * 5 + 1] = ee;
                ((int*)wred)[w * 5 + 2] = bi;
            }
        }
        __syncthreads();

        // ==== R4': warp 0 merges 16 warp triples + state + mask update ====
        if (w == 0) {
            float m_w = (lane < 16) ? wred[lane * 5 + 0] : NEGV;
            float s_w = (lane < 16) ? wred[lane * 5 + 1] : 0.f;
            int   i_w = (lane < 16) ? ((int*)wred)[lane * 5 + 2] : 0x7fffffff;
            float M = m_w; int BI = i_w;
#pragma unroll
            for (int off = 1; off <= 8; off <<= 1) {
                float ov = __shfl_xor_sync(0xffffffffu, M, off);
                int   oi = __shfl_xor_sync(0xffffffffu, BI, off);
                if (ov > M || (ov == M && oi < BI)) { M = ov; BI = oi; }
            }
            float sc = s_w * expf(m_w - M);
#pragma unroll
            for (int off = 1; off <= 8; off <<= 1) sc += __shfl_xor_sync(0xffffffffu, sc, off);

            if (lane == 0) {
                int idx = BI;
                imisc[0] = idx;
                if (imisc[1] < Nn - 1) misc[2] += -logf(sc);
                out[(size_t)b * ns + step] = (float)idx;
                float c = (idx == 0) ? misc[1] : misc[0] - dem[idx];
                misc[0] = c;
                if (idx > 0 && mask1[idx] == 0.f) { mask1[idx] = 1.f; imisc[1] += 1; }
            }
            __syncwarp();
            float capc = misc[0];
            int idx = imisc[0];
            const int li = (lane < NP4) ? lane : 0;
            float4 dm = reinterpret_cast<const float4*>(dem)[li];
            float4 m1 = reinterpret_cast<const float4*>(mask1)[li];
            float4 mk;
            mk.x = (m1.x > 0.f || dm.x > capc) ? 1.f : 0.f;
            mk.y = (m1.y > 0.f || dm.y > capc) ? 1.f : 0.f;
            mk.z = (m1.z > 0.f || dm.z > capc) ? 1.f : 0.f;
            mk.w = (m1.w > 0.f || dm.w > capc) ? 1.f : 0.f;
            bool mine = true;
            if (lane < NP4) {
                if (lane > 0) mine = (mk.x > 0.f) && (mk.y > 0.f) && (mk.z > 0.f) && (mk.w > 0.f);
                else          mine = (mk.y > 0.f) && (mk.z > 0.f) && (mk.w > 0.f);
            }
            bool allc = __all_sync(0xffffffffu, mine);
            if (lane == 0) mk.x = allc ? 0.f : ((idx == 0) ? 1.f : 0.f);
            if (lane < NP4) reinterpret_cast<float4*>(MSK)[lane] = mk;
        }
        __syncthreads();
    }

    if (t == 0) out[(size_t)B * ns + b] = misc[2];
}

// =====================================================================
extern "C" void kernel_launch(void* const* d_in, const int* in_sizes, int n_in,
                              void* d_out, int out_size)
{
    const float* enc      = (const float*)d_in[0];
    const float* pool     = (const float*)d_in[1];
    const float* capacity = (const float*)d_in[2];
    const float* demand   = (const float*)d_in[3];
    const float* fc_w     = (const float*)d_in[4];
    const float* fc1_w    = (const float*)d_in[5];
    const float* Wq       = (const float*)d_in[6];
    const float* Wk       = (const float*)d_in[7];
    const float* Wv       = (const float*)d_in[8];
    const float* Wo       = (const float*)d_in[9];
    const float* Wk2      = (const float*)d_in[10];
    const int*   Tptr     = (const int*)d_in[12];

    int B  = in_sizes[0] / (Nn * Hh);          // 1024
    int ns = out_size / B - 1;                 // 128
    float* out = (float*)d_out;

    weights_kernel<<<768, 128>>>(fc_w, fc1_w, Wq, Wk, Wv, Wo, Wk2);
    qpool_kernel<<<B, 128>>>(pool);

    cudaFuncSetAttribute(encproj_kernel, cudaFuncAttributeMaxDynamicSharedMemorySize, Nn * Hh * 4);
    encproj_kernel<<<B, 512, Nn * Hh * 4>>>(enc);

    cudaFuncSetAttribute(decode_kernel, cudaFuncAttributeMaxDynamicSharedMemorySize, DEC_SMEM_BYTES);
    decode_kernel<<<B, 512, DEC_SMEM_BYTES>>>(capacity, demand, Tptr, out, ns, B);
}

// round 15
// speedup vs baseline: 1.2376x; 1.2376x over previous
#include <cuda_runtime.h>
#include <math.h>

#define Bmax 1024
#define Nn   100
#define Hh   128
#define NHEADS 8
#define HD   16
#define KTS  104        // KT stride (floats) = 26 f4
#define VTS  108        // VT stride = 27 f4 (odd f4)
#define K2S  132        // K2 stride = 33 f4 (odd f4)
#define NP4  26
#define NPF  104
#define NEGV -1000000000.0f

// ---- device scratch ----
__device__ float g_Wcat[Hh * 512];
__device__ float g_Wqf [Hh * (Hh + 1)];
__device__ float g_Wq1 [Hh * Hh];
__device__ float g_qpool[Bmax * Hh];
__device__ float g_EncProj[(size_t)Bmax * 256 * Nn];   // [b][j][n]: K | V
__device__ float g_K2Wt[(size_t)Bmax * Nn * Hh];       // [b][n][h]
__device__ float g_QP  [(size_t)Bmax * Nn * Hh];       // [b][n][h]

// =====================================================================
__global__ void weights_kernel(const float* __restrict__ fc_w,
                               const float* __restrict__ fc1_w,
                               const float* __restrict__ Wq,
                               const float* __restrict__ Wk,
                               const float* __restrict__ Wv,
                               const float* __restrict__ Wo,
                               const float* __restrict__ Wk2)
{
    int bid = blockIdx.x, t = threadIdx.x;
    if (bid < 512) {
        int j = bid;
        float v;
        if (j < 128) {
            v = Wk[j * 128 + t];
        } else if (j < 256) {
            v = Wv[(j - 128) * 128 + t];
        } else if (j < 384) {
            int jp = j - 256;
            float s = 0.f;
            for (int h = 0; h < 128; h++) s += Wk2[h * 128 + t] * Wo[h * 128 + jp];
            v = s;
        } else {
            int hq = j - 384;
            float s = 0.f;
            for (int jj = 0; jj < 128; jj++) s += Wq[hq * 128 + jj] * fc_w[jj * 129 + t];
            v = s;
        }
        g_Wcat[t * 512 + j] = v;
    } else if (bid < 640) {
        int i = bid - 512;
        for (int k = t; k < 129; k += 128) {
            float s = 0.f;
            for (int j = 0; j < 128; j++) s += Wq[i * 128 + j] * fc_w[j * 129 + k];
            g_Wqf[i * 129 + k] = s;
        }
    } else {
        int i = bid - 640;
        float s = 0.f;
        for (int j = 0; j < 128; j++) s += Wq[i * 128 + j] * fc1_w[j * 128 + t];
        g_Wq1[i * 128 + t] = s;
    }
}

// =====================================================================
__global__ void qpool_kernel(const float* __restrict__ pool)
{
    int b = blockIdx.x, h = threadIdx.x;
    float s = 0.f;
    for (int k = 0; k < 128; k++) s += g_Wq1[h * 128 + k] * pool[b * 128 + k];
    g_qpool[b * 128 + h] = s;
}

// =====================================================================
__global__ __launch_bounds__(512, 1)
void encproj_kernel(const float* __restrict__ enc)
{
    extern __shared__ float As[];
    int b = blockIdx.x, t = threadIdx.x;
    for (int i = t; i < Nn * Hh; i += 512) As[i] = enc[(size_t)b * Nn * Hh + i];
    float w[128];
#pragma unroll
    for (int k = 0; k < 128; k++) w[k] = g_Wcat[k * 512 + t];
    __syncthreads();

    float* rowp = (t < 256) ? (g_EncProj + (size_t)b * 256 * Nn + (size_t)t * Nn) : 0;
    float* colp = (t < 384) ? (g_K2Wt + (size_t)b * Nn * Hh + (t - 256))
                            : (g_QP   + (size_t)b * Nn * Hh + (t - 384));

    for (int n0 = 0; n0 < Nn; n0 += 4) {
        float a0 = 0.f, a1 = 0.f, a2 = 0.f, a3 = 0.f;
        const float4* r0 = reinterpret_cast<const float4*>(&As[(n0 + 0) * Hh]);
        const float4* r1 = reinterpret_cast<const float4*>(&As[(n0 + 1) * Hh]);
        const float4* r2 = reinterpret_cast<const float4*>(&As[(n0 + 2) * Hh]);
        const float4* r3 = reinterpret_cast<const float4*>(&As[(n0 + 3) * Hh]);
#pragma unroll
        for (int kk = 0; kk < 32; kk++) {
            float4 x0 = r0[kk];
            a0 += x0.x * w[4*kk] + x0.y * w[4*kk+1] + x0.z * w[4*kk+2] + x0.w * w[4*kk+3];
            float4 x1 = r1[kk];
            a1 += x1.x * w[4*kk] + x1.y * w[4*kk+1] + x1.z * w[4*kk+2] + x1.w * w[4*kk+3];
            float4 x2 = r2[kk];
            a2 += x2.x * w[4*kk] + x2.y * w[4*kk+1] + x2.z * w[4*kk+2] + x2.w * w[4*kk+3];
            float4 x3 = r3[kk];
            a3 += x3.x * w[4*kk] + x3.y * w[4*kk+1] + x3.z * w[4*kk+2] + x3.w * w[4*kk+3];
        }
        if (t < 256) {
            reinterpret_cast<float4*>(rowp + n0)[0] = make_float4(a0, a1, a2, a3);
        } else {
            colp[(size_t)(n0 + 0) * Hh] = a0;
            colp[(size_t)(n0 + 1) * Hh] = a1;
            colp[(size_t)(n0 + 2) * Hh] = a2;
            colp[(size_t)(n0 + 3) * Hh] = a3;
        }
    }
}

// =====================================================================
// Kernel 4: all-smem dense decoder, 3 barriers/step, fused phases.
// =====================================================================
#define DEC_SMEM_FLOATS (Hh*KTS + Hh*VTS + Nn*K2S + Nn*Hh + 128 + 128 + NHEADS*NPF + 128 + NPF + NPF + NPF + 96 + 16)
#define DEC_SMEM_BYTES  (DEC_SMEM_FLOATS * 4)

__global__ __launch_bounds__(512, 1)
void decode_kernel(const float* __restrict__ capacity,
                   const float* __restrict__ demand,
                   const int*   __restrict__ Tptr,
                   float* __restrict__ out, int ns, int B)
{
    extern __shared__ float sm[];
    float* KT    = sm;                    // [128][104]
    float* VT    = KT   + Hh * KTS;       // [128][108]
    float* K2s   = VT   + Hh * VTS;       // [100][132]
    float* QPs   = K2s  + Nn * K2S;       // [100][128]
    float* qp    = QPs  + Nn * Hh;        // 128
    float* wcap  = qp   + 128;            // 128
    float* att   = wcap + 128;            // [8][104]
    float* g     = att  + NHEADS * NPF;   // 128
    float* dem   = g    + 128;            // 104
    float* mask1 = dem  + NPF;            // 104
    float* MSK   = mask1+ NPF;            // 104
    float* wred  = MSK  + NPF;            // 16 warps * 5 + pad
    float* misc  = wred + 96;             // [0]=cap [1]=base [2]=logp [3]=invT
    int*   imisc = (int*)(misc + 8);      // [0]=idx [1]=visited

    const int b = blockIdx.x, t = threadIdx.x;
    const int w = t >> 5, lane = t & 31;

    // ---- load operands ----
    const float* ep = g_EncProj + (size_t)b * 256 * Nn;
    for (int i = t; i < 128 * KTS; i += 512) {
        int j = i / KTS, n = i - j * KTS;
        KT[i] = (n < Nn) ? ep[j * Nn + n] : 0.f;
    }
    for (int i = t; i < 128 * VTS; i += 512) {
        int j = i / VTS, n = i - j * VTS;
        VT[i] = (n < Nn) ? ep[(128 + j) * Nn + n] : 0.f;
    }
    const float* k2g = g_K2Wt + (size_t)b * Nn * Hh;
    for (int i = t; i < Nn * K2S; i += 512) {
        int n = i / K2S, h = i - n * K2S;
        K2s[i] = (h < Hh) ? k2g[n * Hh + h] : 0.f;
    }
    const float* qpg = g_QP + (size_t)b * Nn * Hh;
    for (int i = t; i < Nn * Hh; i += 512) QPs[i] = qpg[i];
    if (t < 128) {
        qp[t]   = g_qpool[b * 128 + t];
        wcap[t] = g_Wqf[t * 129 + 128];
    }
    if (t < NPF) {
        dem[t]   = (t < Nn) ? demand[b * Nn + t] : 3.0e38f;
        mask1[t] = (t < Nn) ? 0.f : 1.f;
    }
    if (t == 0) {
        float c = capacity[b];
        misc[0] = c; misc[1] = capacity[0]; misc[2] = 0.f;
        misc[3] = 1.0f / (float)(*Tptr);
        imisc[0] = 0; imisc[1] = 0;
    }
    __syncthreads();

    // ---- initial mask (idx=0, mask1=0) : warp 0 ----
    if (w == 0) {
        float capc = misc[0];
        const int li = (lane < NP4) ? lane : 0;
        float4 dm = reinterpret_cast<const float4*>(dem)[li];
        float4 m1 = reinterpret_cast<const float4*>(mask1)[li];
        float4 mk;
        mk.x = (m1.x > 0.f || dm.x > capc) ? 1.f : 0.f;
        mk.y = (m1.y > 0.f || dm.y > capc) ? 1.f : 0.f;
        mk.z = (m1.z > 0.f || dm.z > capc) ? 1.f : 0.f;
        mk.w = (m1.w > 0.f || dm.w > capc) ? 1.f : 0.f;
        bool mine = true;
        if (lane < NP4) {
            if (lane > 0) mine = (mk.x > 0.f) && (mk.y > 0.f) && (mk.z > 0.f) && (mk.w > 0.f);
            else          mine = (mk.y > 0.f) && (mk.z > 0.f) && (mk.w > 0.f);
        }
        bool allc = __all_sync(0xffffffffu, mine);
        if (lane == 0) mk.x = allc ? 0.f : 1.f;
        if (lane < NP4) reinterpret_cast<float4*>(MSK)[lane] = mk;
    }
    __syncthreads();

    const float4* KT4  = reinterpret_cast<const float4*>(KT);
    const float4* VT4  = reinterpret_cast<const float4*>(VT);
    const float4* MSK4 = reinterpret_cast<const float4*>(MSK);
    const float4* g4   = reinterpret_cast<const float4*>(g);
    float4* att4 = reinterpret_cast<float4*>(att);

    for (int step = 0; step < ns; step++) {
        // ==== F1: q chunk + scores + softmax + g (warp w = head w) ====
        if (w < NHEADS) {
            int sidx = imisc[0];
            float capc = misc[0];
            float qd = 0.f;
            if (lane < HD) {
                int hh = w * HD + lane;
                qd = qp[hh] + QPs[sidx * Hh + hh] + capc * wcap[hh];
            }
            float4 acc = make_float4(0.f, 0.f, 0.f, 0.f);
            const int li = (lane < NP4) ? lane : 0;
            const float4* kb = KT4 + (w * HD) * NP4;
#pragma unroll
            for (int d = 0; d < HD; d++) {
                float qv = __shfl_sync(0xffffffffu, qd, d);
                float4 kv = kb[d * NP4 + li];
                acc.x += qv * kv.x; acc.y += qv * kv.y;
                acc.z += qv * kv.z; acc.w += qv * kv.w;
            }
            float4 mv = MSK4[li];
            float4 v;
            v.x = (lane < NP4 && mv.x == 0.f) ? acc.x * 0.25f : NEGV;
            v.y = (lane < NP4 && mv.y == 0.f) ? acc.y * 0.25f : NEGV;
            v.z = (lane < NP4 && mv.z == 0.f) ? acc.z * 0.25f : NEGV;
            v.w = (lane < NP4 && mv.w == 0.f) ? acc.w * 0.25f : NEGV;
            float m = fmaxf(fmaxf(v.x, v.y), fmaxf(v.z, v.w));
#pragma unroll
            for (int off = 16; off; off >>= 1) m = fmaxf(m, __shfl_xor_sync(0xffffffffu, m, off));
            float4 e;
            e.x = expf(v.x - m); e.y = expf(v.y - m);
            e.z = expf(v.z - m); e.w = expf(v.w - m);
            float ss = e.x + e.y + e.z + e.w;
#pragma unroll
            for (int off = 16; off; off >>= 1) ss += __shfl_xor_sync(0xffffffffu, ss, off);
            float inv = 1.f / ss;
            if (lane < NP4)
                att4[w * NP4 + lane] = make_float4(e.x*inv, e.y*inv, e.z*inv, e.w*inv);
            __syncwarp();

            // fused g: warp w computes g[16w .. 16w+15] from its own att
            int hl = lane >> 1, half = lane & 1;
            int h = w * HD + hl;
            const float4* ap = att4 + w * NP4;
            const float4* vp = VT4 + h * 27;
            float sg = 0.f;
#pragma unroll
            for (int j = 0; j < 13; j++) {
                int k = half * 13 + j;
                float4 a = ap[k];
                float4 vv = vp[k];
                sg += a.x*vv.x + a.y*vv.y + a.z*vv.z + a.w*vv.w;
            }
            sg += __shfl_xor_sync(0xffffffffu, sg, 1);
            if (half == 0) g[h] = sg;
        }
        __syncthreads();

        // ==== F2: u row dot (smem K2) + fused per-warp argmax/logsumexp ====
        {
            int n = t >> 2, p4 = t & 3;
            int nc = (n < Nn) ? n : 0;
            const float4* kp = reinterpret_cast<const float4*>(K2s) + nc * 33 + p4 * 8;
            const float4* gp = g4 + p4 * 8;
            float su = 0.f;
#pragma unroll
            for (int r = 0; r < 8; r++) {
                int rr = (r + 2 * p4) & 7;               // bank stagger
                float4 kv = kp[rr], gv = gp[rr];
                su += kv.x*gv.x + kv.y*gv.y + kv.z*gv.z + kv.w*gv.w;
            }
            su += __shfl_xor_sync(0xffffffffu, su, 1);
            su += __shfl_xor_sync(0xffffffffu, su, 2);

            float invT = misc[3];
            bool own = (p4 == 0) && (n < Nn);
            float uval = NEGV;
            if (own) uval = (MSK[n] == 0.f) ? 10.f * tanhf(su * 0.08838834764831845f) : NEGV;
            float vv = uval * invT;
            int   vi = own ? n : 0x7fffffff;
            float bw = vv; int bi = vi;
#pragma unroll
            for (int off = 4; off <= 16; off <<= 1) {
                float ov = __shfl_xor_sync(0xffffffffu, bw, off);
                int   oi = __shfl_xor_sync(0xffffffffu, bi, off);
                if (ov > bw || (ov == bw && oi < bi)) { bw = ov; bi = oi; }
            }
            float ee = own ? expf(vv - bw) : 0.f;
#pragma unroll
            for (int off = 4; off <= 16; off <<= 1) ee += __shfl_xor_sync(0xffffffffu, ee, off);
            if (lane == 0) {
                wred[w * 5 + 0] = bw;
                wred[w * 5 + 1] = ee;
                ((int*)wred)[w * 5 + 2] = bi;
            }
        }
        __syncthreads();

        // ==== F3: warp 0 merges 16 warp triples + state + mask update ====
        if (w == 0) {
            float m_w = (lane < 16) ? wred[lane * 5 + 0] : NEGV;
            float s_w = (lane < 16) ? wred[lane * 5 + 1] : 0.f;
            int   i_w = (lane < 16) ? ((int*)wred)[lane * 5 + 2] : 0x7fffffff;
            float M = m_w; int BI = i_w;
#pragma unroll
            for (int off = 1; off <= 8; off <<= 1) {
                float ov = __shfl_xor_sync(0xffffffffu, M, off);
                int   oi = __shfl_xor_sync(0xffffffffu, BI, off);
                if (ov > M || (ov == M && oi < BI)) { M = ov; BI = oi; }
            }
            float sc = s_w * expf(m_w - M);
#pragma unroll
            for (int off = 1; off <= 8; off <<= 1) sc += __shfl_xor_sync(0xffffffffu, sc, off);

            if (lane == 0) {
                int idx = BI;
                imisc[0] = idx;
                if (imisc[1] < Nn - 1) misc[2] += -logf(sc);
                out[(size_t)b * ns + step] = (float)idx;
                float c = (idx == 0) ? misc[1] : misc[0] - dem[idx];
                misc[0] = c;
                if (idx > 0 && mask1[idx] == 0.f) { mask1[idx] = 1.f; imisc[1] += 1; }
            }
            __syncwarp();
            float capc = misc[0];
            int idx = imisc[0];
            const int li = (lane < NP4) ? lane : 0;
            float4 dm = reinterpret_cast<const float4*>(dem)[li];
            float4 m1 = reinterpret_cast<const float4*>(mask1)[li];
            float4 mk;
            mk.x = (m1.x > 0.f || dm.x > capc) ? 1.f : 0.f;
            mk.y = (m1.y > 0.f || dm.y > capc) ? 1.f : 0.f;
            mk.z = (m1.z > 0.f || dm.z > capc) ? 1.f : 0.f;
            mk.w = (m1.w > 0.f || dm.w > capc) ? 1.f : 0.f;
            bool mine = true;
            if (lane < NP4) {
                if (lane > 0) mine = (mk.x > 0.f) && (mk.y > 0.f) && (mk.z > 0.f) && (mk.w > 0.f);
                else          mine = (mk.y > 0.f) && (mk.z > 0.f) && (mk.w > 0.f);
            }
            bool allc = __all_sync(0xffffffffu, mine);
            if (lane == 0) mk.x = allc ? 0.f : ((idx == 0) ? 1.f : 0.f);
            if (lane < NP4) reinterpret_cast<float4*>(MSK)[lane] = mk;
        }
        __syncthreads();
    }

    if (t == 0) out[(size_t)B * ns + b] = misc[2];
}

// =====================================================================
extern "C" void kernel_launch(void* const* d_in, const int* in_sizes, int n_in,
                              void* d_out, int out_size)
{
    const float* enc      = (const float*)d_in[0];
    const float* pool     = (const float*)d_in[1];
    const float* capacity = (const float*)d_in[2];
    const float* demand   = (const float*)d_in[3];
    const float* fc_w     = (const float*)d_in[4];
    const float* fc1_w    = (const float*)d_in[5];
    const float* Wq       = (const float*)d_in[6];
    const float* Wk       = (const float*)d_in[7];
    const float* Wv       = (const float*)d_in[8];
    const float* Wo       = (const float*)d_in[9];
    const float* Wk2      = (const float*)d_in[10];
    const int*   Tptr     = (const int*)d_in[12];

    int B  = in_sizes[0] / (Nn * Hh);          // 1024
    int ns = out_size / B - 1;                 // 128
    float* out = (float*)d_out;

    weights_kernel<<<768, 128>>>(fc_w, fc1_w, Wq, Wk, Wv, Wo, Wk2);
    qpool_kernel<<<B, 128>>>(pool);

    cudaFuncSetAttribute(encproj_kernel, cudaFuncAttributeMaxDynamicSharedMemorySize, Nn * Hh * 4);
    encproj_kernel<<<B, 512, Nn * Hh * 4>>>(enc);

    cudaFuncSetAttribute(decode_kernel, cudaFuncAttributeMaxDynamicSharedMemorySize, DEC_SMEM_BYTES);
    decode_kernel<<<B, 512, DEC_SMEM_BYTES>>>(capacity, demand, Tptr, out, ns, B);
}